// round 5
// baseline (speedup 1.0000x reference)
#include <cuda_runtime.h>
#include <math.h>

// ---------------------------------------------------------------------------
// DAFCN forward, B=1024, T=50, F=48, D=512.
// Attention branch (wq*/wk*, dvb, attended) is dead: combined[:, :, :10]
// selects only gcn_out. Compute FFC (direct DFT) + GCN chain + MLP.
// R2: gconv reassociated to (att@X)@W; 12x4 thread tiles; vectorized LDS;
//     194KB SMEM (L1D ~34KB); W read once per CTA per layer via L1 reuse.
// ---------------------------------------------------------------------------

typedef unsigned long long ull;

#define PI_F 3.14159265358979f
#define W0_DCT 0.18257418583505537f  /* sqrt(1/30) */
#define W1_DCT 0.2581988897471611f   /* sqrt(2/30) */

__device__ float g_ffc[1024 * 48 * 10];  // [b][f48][t<10]

// ---- packed f32x2 helpers -------------------------------------------------
__device__ __forceinline__ ull pk2(float lo, float hi) {
    ull r;
    asm("mov.b64 %0, {%1, %2};" : "=l"(r) : "f"(lo), "f"(hi));
    return r;
}
__device__ __forceinline__ void fma2f(ull &d, ull a, ull b) {
    asm("fma.rn.f32x2 %0, %1, %2, %0;" : "+l"(d) : "l"(a), "l"(b));
}
__device__ __forceinline__ float2 up2(ull v) {
    float lo, hi;
    asm("mov.b64 {%0, %1}, %2;" : "=f"(lo), "=f"(hi) : "l"(v));
    return make_float2(lo, hi);
}

// ===========================================================================
// FFC kernel: one block per (b, g), g = f48 % 16, c = f48 / 16.
// ===========================================================================
__global__ void ffc_kernel(const float* __restrict__ seq,
                           const float* __restrict__ wl,
                           const float* __restrict__ wg) {
    int bx = blockIdx.x;
    int b = bx >> 4;
    int g = bx & 15;
    int tid = threadIdx.x;

    __shared__ float sXf[3][60];
    __shared__ float sV[6][31];
    __shared__ float sc[60], ss[60];
    __shared__ float sWg[36], sWl[9];

    if (tid < 60) {
        float a = 6.283185307179586f * (float)tid / 60.0f;
        sc[tid] = cosf(a);
        ss[tid] = sinf(a);
    }
    if (tid < 36) sWg[tid] = wg[tid];
    if (tid < 9)  sWl[tid] = wl[tid];
    for (int i = tid; i < 180; i += 64) {
        int c = i / 60, t = i % 60;
        int tsrc = (t < 50) ? t : 49;
        sXf[c][t] = seq[b * 2400 + tsrc * 48 + c * 16 + g];
    }
    __syncthreads();

    if (tid < 31) {
        int k = tid;
        float re0 = 0.f, re1 = 0.f, re2 = 0.f, im0 = 0.f, im1 = 0.f, im2 = 0.f;
        int idx = 0;
        for (int t = 0; t < 60; t++) {
            float co = sc[idx], si = ss[idx];
            float x0 = sXf[0][t], x1 = sXf[1][t], x2 = sXf[2][t];
            re0 += x0 * co; im0 -= x0 * si;
            re1 += x1 * co; im1 -= x1 * si;
            re2 += x2 * co; im2 -= x2 * si;
            idx += k; if (idx >= 60) idx -= 60;
        }
        float U[6] = {re0, re1, re2, im0, im1, im2};
        #pragma unroll
        for (int o = 0; o < 6; o++) {
            float a = 0.f;
            #pragma unroll
            for (int c = 0; c < 6; c++) a += sWg[o * 6 + c] * U[c];
            sV[o][k] = (a > 0.f) ? a : 0.f;
        }
    }
    __syncthreads();

    if (tid < 30) {
        int o = tid / 10, t = tid % 10;
        float spec = sV[o][0] + ((t & 1) ? -sV[o][30] : sV[o][30]);
        int idx = t;
        for (int k = 1; k < 30; k++) {
            spec += 2.0f * (sV[o][k] * sc[idx] - sV[o + 3][k] * ss[idx]);
            idx += t; if (idx >= 60) idx -= 60;
        }
        spec *= (1.0f / 60.0f);
        float v = spec;
        #pragma unroll
        for (int c = 0; c < 3; c++) v += sWl[o * 3 + c] * sXf[c][t];
        g_ffc[b * 480 + (o * 16 + g) * 10 + t] = v;
    }
}

// ===========================================================================
// GCN mega-kernel: 1 CTA per batch, 512 threads.
// Thread tile: 12 rows x 4 cols. cgid = tid & 127 (col group), rg = tid >> 7.
// ===========================================================================

// dst = tanh(Z @ W + bias)   (mode 0: store;  mode 1: dst += ...)
// Accumulate fully in registers, barrier, then write -> in-place safe.
__device__ __forceinline__ void big_gemm(const float* Z,
                                         const float* __restrict__ W,
                                         const float* __restrict__ bias,
                                         float* dst, int mode) {
    const int cgid = threadIdx.x & 127;
    const int rg = threadIdx.x >> 7;
    const int r0 = rg * 12, n0 = cgid * 4;
    ull acc[24];
    #pragma unroll
    for (int i = 0; i < 24; i++) acc[i] = 0ull;

    const float4* Wb = reinterpret_cast<const float4*>(W + n0);

    for (int k4 = 0; k4 < 128; k4++) {
        if ((k4 & 3) == 0) __syncthreads();   // keep warps in L1-reuse lockstep
        float4 w0 = __ldg(Wb + (k4 * 4 + 0) * 128);
        float4 w1 = __ldg(Wb + (k4 * 4 + 1) * 128);
        float4 w2 = __ldg(Wb + (k4 * 4 + 2) * 128);
        float4 w3 = __ldg(Wb + (k4 * 4 + 3) * 128);
        ull wp[8];
        wp[0] = pk2(w0.x, w0.y); wp[1] = pk2(w0.z, w0.w);
        wp[2] = pk2(w1.x, w1.y); wp[3] = pk2(w1.z, w1.w);
        wp[4] = pk2(w2.x, w2.y); wp[5] = pk2(w2.z, w2.w);
        wp[6] = pk2(w3.x, w3.y); wp[7] = pk2(w3.z, w3.w);
        #pragma unroll
        for (int i = 0; i < 12; i++) {
            float4 xv = *reinterpret_cast<const float4*>(Z + (r0 + i) * 512 + k4 * 4);
            ull a;
            a = pk2(xv.x, xv.x); fma2f(acc[2*i], a, wp[0]); fma2f(acc[2*i+1], a, wp[1]);
            a = pk2(xv.y, xv.y); fma2f(acc[2*i], a, wp[2]); fma2f(acc[2*i+1], a, wp[3]);
            a = pk2(xv.z, xv.z); fma2f(acc[2*i], a, wp[4]); fma2f(acc[2*i+1], a, wp[5]);
            a = pk2(xv.w, xv.w); fma2f(acc[2*i], a, wp[6]); fma2f(acc[2*i+1], a, wp[7]);
        }
    }
    __syncthreads();   // all reads of Z done -> safe to overwrite
    float4 bv = __ldg(reinterpret_cast<const float4*>(bias + n0));
    #pragma unroll
    for (int i = 0; i < 12; i++) {
        float2 v0 = up2(acc[2*i]), v1 = up2(acc[2*i+1]);
        float o0 = tanhf(v0.x + bv.x);
        float o1 = tanhf(v0.y + bv.y);
        float o2 = tanhf(v1.x + bv.z);
        float o3 = tanhf(v1.y + bv.w);
        float4* p = reinterpret_cast<float4*>(dst + (r0 + i) * 512 + n0);
        if (mode == 0) {
            *p = make_float4(o0, o1, o2, o3);
        } else {
            float4 old = *p;
            *p = make_float4(old.x + o0, old.y + o1, old.z + o2, old.w + o3);
        }
    }
    __syncthreads();
}

// dst = att @ Y   (att 48x48 from gmem, Y 48x512 in SMEM). In-place safe.
__device__ __forceinline__ void att_mul(const float* Y,
                                        const float* __restrict__ att,
                                        float* dst) {
    const int cgid = threadIdx.x & 127;
    const int rg = threadIdx.x >> 7;
    const int r0 = rg * 12, n0 = cgid * 4;
    ull acc[24];
    #pragma unroll
    for (int i = 0; i < 24; i++) acc[i] = 0ull;

    for (int m4 = 0; m4 < 12; m4++) {
        float4 t0 = *reinterpret_cast<const float4*>(Y + (m4 * 4 + 0) * 512 + n0);
        float4 t1 = *reinterpret_cast<const float4*>(Y + (m4 * 4 + 1) * 512 + n0);
        float4 t2 = *reinterpret_cast<const float4*>(Y + (m4 * 4 + 2) * 512 + n0);
        float4 t3 = *reinterpret_cast<const float4*>(Y + (m4 * 4 + 3) * 512 + n0);
        ull tp[8];
        tp[0] = pk2(t0.x, t0.y); tp[1] = pk2(t0.z, t0.w);
        tp[2] = pk2(t1.x, t1.y); tp[3] = pk2(t1.z, t1.w);
        tp[4] = pk2(t2.x, t2.y); tp[5] = pk2(t2.z, t2.w);
        tp[6] = pk2(t3.x, t3.y); tp[7] = pk2(t3.z, t3.w);
        #pragma unroll
        for (int i = 0; i < 12; i++) {
            float4 av = __ldg(reinterpret_cast<const float4*>(att + (r0 + i) * 48 + m4 * 4));
            ull a;
            a = pk2(av.x, av.x); fma2f(acc[2*i], a, tp[0]); fma2f(acc[2*i+1], a, tp[1]);
            a = pk2(av.y, av.y); fma2f(acc[2*i], a, tp[2]); fma2f(acc[2*i+1], a, tp[3]);
            a = pk2(av.z, av.z); fma2f(acc[2*i], a, tp[4]); fma2f(acc[2*i+1], a, tp[5]);
            a = pk2(av.w, av.w); fma2f(acc[2*i], a, tp[6]); fma2f(acc[2*i+1], a, tp[7]);
        }
    }
    __syncthreads();   // all reads of Y done -> in-place safe
    #pragma unroll
    for (int i = 0; i < 12; i++) {
        float2 v0 = up2(acc[2*i]), v1 = up2(acc[2*i+1]);
        *reinterpret_cast<float4*>(dst + (r0 + i) * 512 + n0) =
            make_float4(v0.x, v0.y, v1.x, v1.y);
    }
    __syncthreads();
}

#define SMEM_FLOATS (24576 + 24576 + 480)

__global__ void __launch_bounds__(512, 1)
gcn_kernel(const float* __restrict__ seq,
           const float* __restrict__ gc1_w,  const float* __restrict__ gc1_att,
           const float* __restrict__ gc1_b,  const float* __restrict__ gcb_w,
           const float* __restrict__ gcb_att,const float* __restrict__ gcb_b,
           const float* __restrict__ gc7_w,  const float* __restrict__ gc7_att,
           const float* __restrict__ gc7_b,  const float* __restrict__ mlp_w1,
           const float* __restrict__ mlp_w2, float* __restrict__ out) {
    extern __shared__ float sm[];
    float* sX   = sm;            // 48*512 (y)
    float* sZ   = sX + 24576;    // 48*512 (att@x / h)
    float* sDct = sZ + 24576;    // 48*10

    const int tid = threadIdx.x;
    const int b = blockIdx.x;
    const float* sq = seq + b * 2400;

    // ---- dct_in[f][d]
    if (tid < 480) {
        int f = tid % 48, d = tid / 48;
        float wd = (d == 0) ? W0_DCT : W1_DCT;
        float acc = 0.f, Sd = 0.f;
        for (int k = 0; k < 30; k++) {
            float cv = wd * cosf(PI_F * ((float)k + 0.5f) * (float)d / 30.0f);
            if (k < 10) acc += cv * sq[(40 + k) * 48 + f];
            else        Sd  += cv;
        }
        acc += Sd * sq[49 * 48 + f];
        sDct[f * 10 + d] = acc;
    }
    __syncthreads();

    // ---- gc1 reassociated: Z1 = att1 @ dct_in  (48x10, temp in sZ)
    if (tid < 480) {
        int n = tid / 10, d = tid % 10;
        float a = 0.f;
        for (int m = 0; m < 48; m++) a += __ldg(gc1_att + n * 48 + m) * sDct[m * 10 + d];
        sZ[n * 10 + d] = a;
    }
    __syncthreads();
    // y = tanh(Z1 @ gc1_w + b1)
    {
        float w10[10];
        #pragma unroll
        for (int d = 0; d < 10; d++) w10[d] = __ldg(gc1_w + d * 512 + tid);
        float bb = __ldg(gc1_b + tid);
        for (int n = 0; n < 48; n++) {
            float a = bb;
            #pragma unroll
            for (int d = 0; d < 10; d++) a += w10[d] * sZ[n * 10 + d];
            sX[n * 512 + tid] = tanhf(a);
        }
    }
    __syncthreads();

    // ---- 4 gconv layers: h = tanh((att@src)@W + b); odd layers: y += h
    #pragma unroll 1
    for (int l = 0; l < 4; l++) {
        const float* att  = gcb_att + l * 2304;
        const float* W    = gcb_w   + l * 262144;
        const float* bias = gcb_b   + l * 512;
        const float* src  = (l & 1) ? sZ : sX;
        att_mul(src, att, sZ);
        big_gemm(sZ, W, bias, (l & 1) ? sX : sZ, l & 1);
    }

    // ---- gc7: Z7 = att7 @ y; gcn_out = Z7 @ gc7_w + b7 + dct_in
    att_mul(sX, gc7_att, sZ);
    if (tid < 480) {
        int n = tid / 10, o = tid % 10;
        float a0 = __ldg(gc7_b + o) + sDct[tid], a1 = 0.f, a2 = 0.f, a3 = 0.f;
        const float* zr = sZ + n * 512;
        for (int k = 0; k < 512; k += 4) {
            a0 += zr[k    ] * __ldg(gc7_w + (k    ) * 10 + o);
            a1 += zr[k + 1] * __ldg(gc7_w + (k + 1) * 10 + o);
            a2 += zr[k + 2] * __ldg(gc7_w + (k + 2) * 10 + o);
            a3 += zr[k + 3] * __ldg(gc7_w + (k + 3) * 10 + o);
        }
        sDct[tid] = a0 + a1 + a2 + a3;   // own element only
    }
    __syncthreads();

    // ---- fused[f][t] (overlay in sZ): t<30 idct, t>=30 ffc
    float* sFused = sZ;          // 1920 floats
    float* sH     = sZ + 2048;   // 48*256 floats
    for (int i = tid; i < 1920; i += 512) {
        int f = i % 48, t = i / 48;
        float v;
        if (t < 30) {
            v = 0.f;
            #pragma unroll
            for (int d = 0; d < 10; d++) {
                float wd = (d == 0) ? W0_DCT : W1_DCT;
                v += wd * cosf(PI_F * ((float)t + 0.5f) * (float)d / 30.0f)
                        * sDct[f * 10 + d];
            }
        } else {
            v = g_ffc[b * 480 + f * 10 + (t - 30)];
        }
        sFused[f * 40 + t] = v;
    }
    __syncthreads();

    // ---- MLP layer 1
    {
        int o = tid & 255;
        int fg = tid >> 8;
        float w1r[40];
        #pragma unroll
        for (int t = 0; t < 40; t++) w1r[t] = __ldg(mlp_w1 + o * 40 + t);
        for (int f = fg * 24; f < fg * 24 + 24; f++) {
            float a = 0.f;
            #pragma unroll
            for (int t = 0; t < 40; t++) a += w1r[t] * sFused[f * 40 + t];
            sH[f * 256 + o] = (a > 0.f) ? a : 0.f;
        }
    }
    __syncthreads();

    // ---- MLP layer 2 (only t'<10); out[b][t'][0][f]
    if (tid < 480) {
        int f = tid / 10, t2 = tid % 10;
        float a0 = 0.f, a1 = 0.f, a2 = 0.f, a3 = 0.f;
        const float* hr = sH + f * 256;
        const float* w2 = mlp_w2 + t2 * 256;
        for (int o = 0; o < 256; o += 4) {
            a0 += hr[o    ] * __ldg(w2 + o);
            a1 += hr[o + 1] * __ldg(w2 + o + 1);
            a2 += hr[o + 2] * __ldg(w2 + o + 2);
            a3 += hr[o + 3] * __ldg(w2 + o + 3);
        }
        out[b * 480 + t2 * 48 + f] = a0 + a1 + a2 + a3;
    }
}

// ===========================================================================
extern "C" void kernel_launch(void* const* d_in, const int* in_sizes, int n_in,
                              void* d_out, int out_size) {
    const float* seq     = (const float*)d_in[0];
    const float* gc1_w   = (const float*)d_in[5];
    const float* gc1_att = (const float*)d_in[6];
    const float* gc1_b   = (const float*)d_in[7];
    const float* gcb_w   = (const float*)d_in[8];
    const float* gcb_att = (const float*)d_in[9];
    const float* gcb_b   = (const float*)d_in[10];
    const float* gc7_w   = (const float*)d_in[11];
    const float* gc7_att = (const float*)d_in[12];
    const float* gc7_b   = (const float*)d_in[13];
    const float* mlp_w1  = (const float*)d_in[14];
    const float* mlp_w2  = (const float*)d_in[15];
    const float* ffc_wl  = (const float*)d_in[16];
    const float* ffc_wg  = (const float*)d_in[17];
    float* out = (float*)d_out;

    int B = in_sizes[0] / 2400;
    size_t smem = SMEM_FLOATS * sizeof(float);
    cudaFuncSetAttribute(gcn_kernel, cudaFuncAttributeMaxDynamicSharedMemorySize,
                         (int)smem);

    ffc_kernel<<<B * 16, 64>>>(seq, ffc_wl, ffc_wg);
    gcn_kernel<<<B, 512, smem>>>(seq, gc1_w, gc1_att, gc1_b, gcb_w, gcb_att,
                                 gcb_b, gc7_w, gc7_att, gc7_b, mlp_w1, mlp_w2,
                                 out);
}

// round 7
// speedup vs baseline: 1.5642x; 1.5642x over previous
#include <cuda_runtime.h>
#include <cuda_bf16.h>
#include <math.h>
#include <cstdint>

// ---------------------------------------------------------------------------
// DAFCN forward, B=1024, T=50, F=48, D=512.
// Attention branch (wq*/wk*, dvb, attended) dead: combined[:,:,:10] = gcn_out.
// R7: big GEMMs via legacy mma.sync bf16 HMMA (tcgen05 rejected by toolchain),
//     bf16x3 split for fp32-grade accuracy. Multi-kernel pipeline:
//     prep_w / ffc / gc1  ->  4x [gemm -> att+tanh]  ->  tail (gc7+MLP).
// ---------------------------------------------------------------------------

#define PI_F 3.14159265358979f
#define W0_DCT 0.18257418583505537f
#define W1_DCT 0.2581988897471611f
#define NB 1024
#define MROWS (NB * 48)

__device__ float         g_X[MROWS * 512];      // fp32 y
__device__ float         g_G[MROWS * 512];      // X@W result
__device__ __nv_bfloat16 g_Ahi[MROWS * 512];    // gemm input hi
__device__ __nv_bfloat16 g_Alo[MROWS * 512];    // gemm input lo
__device__ __nv_bfloat16 g_Whi[4 * 512 * 512];  // W^T [l][n][k] hi
__device__ __nv_bfloat16 g_Wlo[4 * 512 * 512];  // W^T [l][n][k] lo
__device__ float         g_dct[NB * 480];
__device__ float         g_ffc[NB * 480];

__device__ __forceinline__ uint32_t smem_u32(const void* p) {
    uint32_t a;
    asm("{ .reg .u64 t; cvta.to.shared.u64 t, %1; cvt.u32.u64 %0, t; }"
        : "=r"(a) : "l"(p));
    return a;
}

#define CPA16(dst, src) \
    asm volatile("cp.async.cg.shared.global [%0], [%1], 16;" \
                 :: "r"(dst), "l"(src))
#define CP_COMMIT() asm volatile("cp.async.commit_group;" ::: "memory")
#define CP_WAIT(n)  asm volatile("cp.async.wait_group %0;" :: "n"(n) : "memory")

#define LDSM4(r, addr) \
    asm volatile("ldmatrix.sync.aligned.m8n8.x4.shared.b16 {%0,%1,%2,%3}, [%4];" \
        : "=r"((r)[0]), "=r"((r)[1]), "=r"((r)[2]), "=r"((r)[3]) : "r"(addr))

__device__ __forceinline__ void mma_bf16(float* d, const uint32_t* a,
                                         const uint32_t* b) {
    asm volatile(
        "mma.sync.aligned.m16n8k16.row.col.f32.bf16.bf16.f32 "
        "{%0,%1,%2,%3}, {%4,%5,%6,%7}, {%8,%9}, {%0,%1,%2,%3};"
        : "+f"(d[0]), "+f"(d[1]), "+f"(d[2]), "+f"(d[3])
        : "r"(a[0]), "r"(a[1]), "r"(a[2]), "r"(a[3]), "r"(b[0]), "r"(b[1]));
}

// ======================= prep_w: W^T bf16 hi/lo ============================
__global__ void prep_w_kernel(const float* __restrict__ gcb_w) {
    int idx = blockIdx.x * 256 + threadIdx.x;      // 4*512*512
    int l = idx >> 18, k = (idx >> 9) & 511, n = idx & 511;
    float w = gcb_w[l * 262144 + k * 512 + n];
    __nv_bfloat16 hi = __float2bfloat16(w);
    __nv_bfloat16 lo = __float2bfloat16(w - __bfloat162float(hi));
    int dst = l * 262144 + n * 512 + k;
    g_Whi[dst] = hi; g_Wlo[dst] = lo;
}

// ======================= FFC ===============================================
__global__ void ffc_kernel(const float* __restrict__ seq,
                           const float* __restrict__ wl,
                           const float* __restrict__ wg) {
    int bx = blockIdx.x, b = bx >> 4, g = bx & 15, tid = threadIdx.x;
    __shared__ float sXf[3][60], sV[6][31], sc[60], ss[60], sWg[36], sWl[9];
    if (tid < 60) {
        float a = 6.283185307179586f * (float)tid / 60.0f;
        sc[tid] = cosf(a); ss[tid] = sinf(a);
    }
    if (tid < 36) sWg[tid] = wg[tid];
    if (tid < 9)  sWl[tid] = wl[tid];
    for (int i = tid; i < 180; i += 64) {
        int c = i / 60, t = i % 60, tsrc = (t < 50) ? t : 49;
        sXf[c][t] = seq[b * 2400 + tsrc * 48 + c * 16 + g];
    }
    __syncthreads();
    if (tid < 31) {
        int k = tid;
        float re0=0,re1=0,re2=0,im0=0,im1=0,im2=0; int idx = 0;
        for (int t = 0; t < 60; t++) {
            float co = sc[idx], si = ss[idx];
            float x0 = sXf[0][t], x1 = sXf[1][t], x2 = sXf[2][t];
            re0 += x0*co; im0 -= x0*si; re1 += x1*co; im1 -= x1*si;
            re2 += x2*co; im2 -= x2*si;
            idx += k; if (idx >= 60) idx -= 60;
        }
        float U[6] = {re0, re1, re2, im0, im1, im2};
        #pragma unroll
        for (int o = 0; o < 6; o++) {
            float a = 0.f;
            #pragma unroll
            for (int c = 0; c < 6; c++) a += sWg[o * 6 + c] * U[c];
            sV[o][k] = (a > 0.f) ? a : 0.f;
        }
    }
    __syncthreads();
    if (tid < 30) {
        int o = tid / 10, t = tid % 10;
        float spec = sV[o][0] + ((t & 1) ? -sV[o][30] : sV[o][30]);
        int idx = t;
        for (int k = 1; k < 30; k++) {
            spec += 2.0f * (sV[o][k] * sc[idx] - sV[o + 3][k] * ss[idx]);
            idx += t; if (idx >= 60) idx -= 60;
        }
        float v = spec * (1.0f / 60.0f);
        #pragma unroll
        for (int c = 0; c < 3; c++) v += sWl[o * 3 + c] * sXf[c][t];
        g_ffc[b * 480 + (o * 16 + g) * 10 + t] = v;
    }
}

// ======================= gc1 head ==========================================
__global__ void __launch_bounds__(512)
gc1_kernel(const float* __restrict__ seq, const float* __restrict__ gc1_w,
           const float* __restrict__ gc1_att, const float* __restrict__ gc1_b) {
    __shared__ float sDct[480], sZ1[480];
    const int tid = threadIdx.x, b = blockIdx.x;
    const float* sq = seq + b * 2400;
    if (tid < 480) {
        int f = tid % 48, d = tid / 48;
        float wd = (d == 0) ? W0_DCT : W1_DCT;
        float acc = 0.f, Sd = 0.f;
        for (int k = 0; k < 30; k++) {
            float cv = wd * cosf(PI_F * ((float)k + 0.5f) * (float)d / 30.0f);
            if (k < 10) acc += cv * sq[(40 + k) * 48 + f];
            else        Sd  += cv;
        }
        acc += Sd * sq[49 * 48 + f];
        sDct[f * 10 + d] = acc;
        g_dct[b * 480 + f * 10 + d] = acc;
    }
    __syncthreads();
    if (tid < 480) {
        int n = tid / 10, d = tid % 10;
        float a = 0.f;
        for (int m = 0; m < 48; m++) a += __ldg(gc1_att + n * 48 + m) * sDct[m * 10 + d];
        sZ1[n * 10 + d] = a;
    }
    __syncthreads();
    float w10[10];
    #pragma unroll
    for (int d = 0; d < 10; d++) w10[d] = __ldg(gc1_w + d * 512 + tid);
    float bb = __ldg(gc1_b + tid);
    for (int n = 0; n < 48; n++) {
        float a = bb;
        #pragma unroll
        for (int d = 0; d < 10; d++) a += w10[d] * sZ1[n * 10 + d];
        float v = tanhf(a);
        size_t idx = (size_t)(b * 48 + n) * 512 + tid;
        g_X[idx] = v;
        __nv_bfloat16 hi = __float2bfloat16(v);
        g_Ahi[idx] = hi;
        g_Alo[idx] = __float2bfloat16(v - __bfloat162float(hi));
    }
}

// ======================= bf16x3 HMMA GEMM ==================================
// G[m][n] = sum_k A[m][k] * Wt[n][k].  CTA 128x128, 8 warps (2x4), warp 64x32.
// grid (4 n-tiles, 384 m-tiles) -> n varies fastest: wave shares A via L2.
#define A_STRIDE 40   // bf16 per SMEM row (32 data + 8 pad)
#define MAT_SZ (128 * A_STRIDE)
#define GEMM_SMEM (2 * 4 * MAT_SZ * 2)   // 81920 B

__global__ void __launch_bounds__(256, 1)
gemm_kernel(int layer) {
    extern __shared__ __align__(16) __nv_bfloat16 smem[];
    const int tid = threadIdx.x;
    const int lane = tid & 31, wid = tid >> 5;
    const int wm = wid >> 2, wn = wid & 3;
    const int n0 = blockIdx.x * 128;
    const int m0 = blockIdx.y * 128;
    const uint32_t sbase = smem_u32(smem);

    const __nv_bfloat16* Ah = g_Ahi;
    const __nv_bfloat16* Al = g_Alo;
    const __nv_bfloat16* Bh = g_Whi + layer * 262144;
    const __nv_bfloat16* Bl = g_Wlo + layer * 262144;

    float acc[4][4][4];
    #pragma unroll
    for (int i = 0; i < 4; i++)
        #pragma unroll
        for (int j = 0; j < 4; j++)
            #pragma unroll
            for (int r = 0; r < 4; r++) acc[i][j][r] = 0.f;

    const int lrow = tid >> 1;            // 0..127
    const int lq   = (tid & 1) * 2;       // chunk pair: q, q+1  (q in 16B units)

    // ---- async stage loader: 4 matrices x 128 rows x 64B ----
    #define LOAD_STAGE(buf, ks) do { \
        uint32_t dbase = sbase + (uint32_t)((buf) * 4 * MAT_SZ) * 2 + \
                         (uint32_t)(lrow * A_STRIDE + lq * 8) * 2; \
        size_t aoff = (size_t)(m0 + lrow) * 512 + (ks) * 32 + lq * 8; \
        size_t boff = (size_t)(n0 + lrow) * 512 + (ks) * 32 + lq * 8; \
        CPA16(dbase,                    Ah + aoff); \
        CPA16(dbase + 16,               Ah + aoff + 8); \
        CPA16(dbase + MAT_SZ * 2,       Al + aoff); \
        CPA16(dbase + MAT_SZ * 2 + 16,  Al + aoff + 8); \
        CPA16(dbase + MAT_SZ * 4,       Bh + boff); \
        CPA16(dbase + MAT_SZ * 4 + 16,  Bh + boff + 8); \
        CPA16(dbase + MAT_SZ * 6,       Bl + boff); \
        CPA16(dbase + MAT_SZ * 6 + 16,  Bl + boff + 8); \
    } while (0)

    LOAD_STAGE(0, 0);
    CP_COMMIT();

    const int arow = wm * 64 + (lane & 15);
    const int acol = (lane >> 4) * 8;
    const int brow = wn * 32 + (lane & 7) + ((lane >> 4) & 1) * 8;
    const int bcol = ((lane >> 3) & 1) * 8;

    for (int ks = 0; ks < 16; ks++) {
        int buf = ks & 1;
        if (ks + 1 < 16) {
            LOAD_STAGE(buf ^ 1, ks + 1);
            CP_COMMIT();
            CP_WAIT(1);
        } else {
            CP_WAIT(0);
        }
        __syncthreads();

        uint32_t base = sbase + (uint32_t)(buf * 4 * MAT_SZ) * 2;
        #pragma unroll
        for (int sub = 0; sub < 2; sub++) {
            int kb = sub * 16;
            uint32_t ah[4][4], al[4][4], bh[2][4], bl[2][4];
            #pragma unroll
            for (int mt = 0; mt < 4; mt++) {
                LDSM4(ah[mt], base + (uint32_t)((arow + mt * 16) * A_STRIDE + kb + acol) * 2);
                LDSM4(al[mt], base + (uint32_t)(MAT_SZ + (arow + mt * 16) * A_STRIDE + kb + acol) * 2);
            }
            #pragma unroll
            for (int ng = 0; ng < 2; ng++) {
                LDSM4(bh[ng], base + (uint32_t)(2 * MAT_SZ + (brow + ng * 16) * A_STRIDE + kb + bcol) * 2);
                LDSM4(bl[ng], base + (uint32_t)(3 * MAT_SZ + (brow + ng * 16) * A_STRIDE + kb + bcol) * 2);
            }
            #pragma unroll
            for (int mt = 0; mt < 4; mt++) {
                #pragma unroll
                for (int nf = 0; nf < 4; nf++) {
                    const uint32_t* bhf = &bh[nf >> 1][(nf & 1) * 2];
                    const uint32_t* blf = &bl[nf >> 1][(nf & 1) * 2];
                    mma_bf16(acc[mt][nf], ah[mt], bhf);
                    mma_bf16(acc[mt][nf], ah[mt], blf);
                    mma_bf16(acc[mt][nf], al[mt], bhf);
                }
            }
        }
        __syncthreads();
    }

    // ---- epilogue: d-frag layout -> g_G ----
    #pragma unroll
    for (int mt = 0; mt < 4; mt++) {
        int row = m0 + wm * 64 + mt * 16 + (lane >> 2);
        #pragma unroll
        for (int nf = 0; nf < 4; nf++) {
            int col = n0 + wn * 32 + nf * 8 + (lane & 3) * 2;
            *(float2*)&g_G[(size_t)row * 512 + col] =
                make_float2(acc[mt][nf][0], acc[mt][nf][1]);
            *(float2*)&g_G[(size_t)(row + 8) * 512 + col] =
                make_float2(acc[mt][nf][2], acc[mt][nf][3]);
        }
    }
}

// ======================= att + bias + tanh (+residual / emit) ==============
__global__ void __launch_bounds__(512)
att_tanh_kernel(const float* __restrict__ att, const float* __restrict__ bias,
                int residual, int emit) {
    __shared__ float sAtt[2304];
    const int b = blockIdx.x, c = threadIdx.x;
    for (int i = c; i < 2304; i += 512) sAtt[i] = att[i];
    __syncthreads();
    float g[48];
    const float* Gb = g_G + (size_t)b * 48 * 512 + c;
    #pragma unroll
    for (int m = 0; m < 48; m++) g[m] = Gb[(size_t)m * 512];
    float bb = __ldg(bias + c);
    for (int n = 0; n < 48; n++) {
        float a = bb;
        const float* ar = sAtt + n * 48;
        #pragma unroll
        for (int m = 0; m < 48; m++) a += ar[m] * g[m];
        float t = tanhf(a);
        size_t idx = (size_t)(b * 48 + n) * 512 + c;
        float v = t;
        if (residual) { v = g_X[idx] + t; g_X[idx] = v; }
        if (emit) {
            __nv_bfloat16 hi = __float2bfloat16(v);
            g_Ahi[idx] = hi;
            g_Alo[idx] = __float2bfloat16(v - __bfloat162float(hi));
        }
    }
}

// ======================= tail: gc7 + fused + MLP ===========================
#define TAIL_SMEM ((480 + 480 + 480 + 5120 + 1920 + 12288) * 4)
__global__ void __launch_bounds__(512)
tail_kernel(const float* __restrict__ gc7_w, const float* __restrict__ gc7_att,
            const float* __restrict__ gc7_b, const float* __restrict__ mlp_w1,
            const float* __restrict__ mlp_w2, float* __restrict__ out) {
    extern __shared__ float sm[];
    float* sDct = sm;
    float* sP   = sDct + 480;
    float* sOut = sP + 480;
    float* sW7  = sOut + 480;      // [o][k] 10x512
    float* sFused = sW7 + 5120;    // 48x40
    float* sH   = sFused + 1920;   // 48x256
    const int tid = threadIdx.x, b = blockIdx.x;

    if (tid < 480) sDct[tid] = g_dct[b * 480 + tid];
    for (int i = tid; i < 5120; i += 512) {
        int o = i / 512, k = i % 512;
        sW7[o * 512 + k] = __ldg(gc7_w + k * 10 + o);
    }
    __syncthreads();
    if (tid < 480) {
        int m = tid / 10, o = tid % 10;
        const float* yr = g_X + (size_t)(b * 48 + m) * 512;
        const float* wr = sW7 + o * 512;
        float a0=0,a1=0,a2=0,a3=0;
        for (int k = 0; k < 512; k += 4) {
            float4 y4 = *(const float4*)(yr + k);
            float4 w4 = *(const float4*)(wr + k);
            a0 += y4.x*w4.x; a1 += y4.y*w4.y; a2 += y4.z*w4.z; a3 += y4.w*w4.w;
        }
        sP[tid] = a0 + a1 + a2 + a3;
    }
    __syncthreads();
    if (tid < 480) {
        int n = tid / 10, o = tid % 10;
        float a = __ldg(gc7_b + o) + sDct[tid];
        for (int m = 0; m < 48; m++) a += __ldg(gc7_att + n * 48 + m) * sP[m * 10 + o];
        sOut[tid] = a;
    }
    __syncthreads();
    for (int i = tid; i < 1920; i += 512) {
        int f = i % 48, t = i / 48;
        float v;
        if (t < 30) {
            v = 0.f;
            #pragma unroll
            for (int d = 0; d < 10; d++) {
                float wd = (d == 0) ? W0_DCT : W1_DCT;
                v += wd * cosf(PI_F * ((float)t + 0.5f) * (float)d / 30.0f)
                        * sOut[f * 10 + d];
            }
        } else v = g_ffc[b * 480 + f * 10 + (t - 30)];
        sFused[f * 40 + t] = v;
    }
    __syncthreads();
    {
        int o = tid & 255, fg = tid >> 8;
        float w1r[40];
        #pragma unroll
        for (int t = 0; t < 40; t++) w1r[t] = __ldg(mlp_w1 + o * 40 + t);
        for (int f = fg * 24; f < fg * 24 + 24; f++) {
            float a = 0.f;
            #pragma unroll
            for (int t = 0; t < 40; t++) a += w1r[t] * sFused[f * 40 + t];
            sH[f * 256 + o] = (a > 0.f) ? a : 0.f;
        }
    }
    __syncthreads();
    if (tid < 480) {
        int f = tid / 10, t2 = tid % 10;
        float a0=0,a1=0,a2=0,a3=0;
        const float* hr = sH + f * 256;
        const float* w2 = mlp_w2 + t2 * 256;
        for (int o = 0; o < 256; o += 4) {
            a0 += hr[o]*__ldg(w2+o);     a1 += hr[o+1]*__ldg(w2+o+1);
            a2 += hr[o+2]*__ldg(w2+o+2); a3 += hr[o+3]*__ldg(w2+o+3);
        }
        out[b * 480 + t2 * 48 + f] = a0 + a1 + a2 + a3;
    }
}

// ===========================================================================
extern "C" void kernel_launch(void* const* d_in, const int* in_sizes, int n_in,
                              void* d_out, int out_size) {
    const float* seq     = (const float*)d_in[0];
    const float* gc1_w   = (const float*)d_in[5];
    const float* gc1_att = (const float*)d_in[6];
    const float* gc1_b   = (const float*)d_in[7];
    const float* gcb_w   = (const float*)d_in[8];
    const float* gcb_att = (const float*)d_in[9];
    const float* gcb_b   = (const float*)d_in[10];
    const float* gc7_w   = (const float*)d_in[11];
    const float* gc7_att = (const float*)d_in[12];
    const float* gc7_b   = (const float*)d_in[13];
    const float* mlp_w1  = (const float*)d_in[14];
    const float* mlp_w2  = (const float*)d_in[15];
    const float* ffc_wl  = (const float*)d_in[16];
    const float* ffc_wg  = (const float*)d_in[17];
    float* out = (float*)d_out;

    int B = in_sizes[0] / 2400;           // 1024
    int gm = (B * 48) / 128;              // 384 m-tiles

    cudaFuncSetAttribute(gemm_kernel,
        cudaFuncAttributeMaxDynamicSharedMemorySize, GEMM_SMEM);
    cudaFuncSetAttribute(tail_kernel,
        cudaFuncAttributeMaxDynamicSharedMemorySize, TAIL_SMEM);

    prep_w_kernel<<<4096, 256>>>(gcb_w);
    ffc_kernel<<<B * 16, 64>>>(seq, ffc_wl, ffc_wg);
    gc1_kernel<<<B, 512>>>(seq, gc1_w, gc1_att, gc1_b);

    for (int l = 0; l < 4; l++) {
        gemm_kernel<<<dim3(4, gm), 256, GEMM_SMEM>>>(l);
        att_tanh_kernel<<<B, 512>>>(gcb_att + l * 2304, gcb_b + l * 512,
                                    l & 1, (l < 3) ? 1 : 0);
    }
    tail_kernel<<<B, 512, TAIL_SMEM>>>(gc7_w, gc7_att, gc7_b,
                                       mlp_w1, mlp_w2, out);
}